// round 3
// baseline (speedup 1.0000x reference)
#include <cuda_runtime.h>

// ---------------------------------------------------------------------------
// GAT forward (fused pipeline, 3 kernels):
//   1) gemm_fused : h = x@W (f32x2 packed FMA), plus per-node a_src/a_dst,
//                   self-loop weight into s, out initialized with w_self*h.
//   2) edge_accum : unnormalized message scatter with float4 vector atomics.
//   3) finalize   : out = tanh(out / s + bias).
// Softmax max-shift is skipped (|e| bounded ~10, exp cannot overflow fp32;
// result identical after normalization).
// ---------------------------------------------------------------------------

#define NMAX 100000

__device__ __align__(16) float g_h[(size_t)NMAX * 128];
__device__ __align__(16) float g_asrc[NMAX * 4];
__device__ __align__(16) float g_adst[NMAX * 4];
__device__ __align__(16) float g_s[NMAX * 4];

__device__ __forceinline__ unsigned long long pack2(float lo, float hi) {
    unsigned long long r;
    asm("mov.b64 %0, {%1, %2};" : "=l"(r) : "f"(lo), "f"(hi));
    return r;
}
__device__ __forceinline__ void unpack2(unsigned long long v, float& lo, float& hi) {
    asm("mov.b64 {%0, %1}, %2;" : "=f"(lo), "=f"(hi) : "l"(v));
}
__device__ __forceinline__ void ffma2(unsigned long long& d,
                                      unsigned long long a,
                                      unsigned long long b) {
    asm("fma.rn.f32x2 %0, %1, %2, %0;" : "+l"(d) : "l"(a), "l"(b));
}

// ---------------------------------------------------------------------------
// Kernel 1: fused GEMM + node init.
// 128-row x 128-col tile, K chunked by 32, 256 threads, 8x8 per thread via
// packed f32x2 FMA (2 FLOP-pairs per fma-pipe slot).
// Epilogue: writes g_h, out=w_self*h, g_asrc/g_adst/g_s.
// ---------------------------------------------------------------------------
__global__ void gemm_fused(const float* __restrict__ x,
                           const float* __restrict__ W,
                           const float* __restrict__ att_src,
                           const float* __restrict__ att_dst,
                           float* __restrict__ out, int N) {
    __shared__ float sx[128][33];   // [row][k-within-chunk], +1 pad
    __shared__ float sW[32][128];   // [k-within-chunk][col]

    const int tid = threadIdx.x;
    const int rbase = blockIdx.x * 128;
    const int tx = tid & 15;        // col group (8 cols: tx*8..tx*8+7, one head)
    const int ty = tid >> 4;        // row group (8 rows)

    unsigned long long acc2[8][4];
#pragma unroll
    for (int i = 0; i < 8; i++)
#pragma unroll
        for (int j = 0; j < 4; j++) acc2[i][j] = 0ULL;

    for (int kc = 0; kc < 128; kc += 32) {
        __syncthreads();
        // stage x tile: 128 rows x 32 cols (zero-fill OOB rows)
        for (int i = tid; i < 1024; i += 256) {
            int row = i >> 3;
            int c4 = i & 7;
            float4 v = make_float4(0.f, 0.f, 0.f, 0.f);
            if (rbase + row < N)
                v = *(const float4*)(x + (size_t)(rbase + row) * 128 + kc + c4 * 4);
            float* p = &sx[row][c4 * 4];
            p[0] = v.x; p[1] = v.y; p[2] = v.z; p[3] = v.w;
        }
        // stage W chunk: 32 rows x 128 cols
        for (int i = tid; i < 1024; i += 256) {
            int row = i >> 5;
            int c4 = i & 31;
            *(float4*)&sW[row][c4 * 4] =
                *(const float4*)(W + (size_t)(kc + row) * 128 + c4 * 4);
        }
        __syncthreads();

#pragma unroll
        for (int k = 0; k < 32; k++) {
            ulonglong2 b01 = *(const ulonglong2*)&sW[k][tx * 8];
            ulonglong2 b23 = *(const ulonglong2*)&sW[k][tx * 8 + 4];
            unsigned long long b2[4] = {b01.x, b01.y, b23.x, b23.y};
#pragma unroll
            for (int i = 0; i < 8; i++) {
                float av = sx[ty * 8 + i][k];
                unsigned long long a2 = pack2(av, av);
#pragma unroll
                for (int j = 0; j < 4; j++) ffma2(acc2[i][j], a2, b2[j]);
            }
        }
    }

    // ---- fused epilogue ----
    // att weights for this thread's 8 columns
    float atts[8], attd[8];
    *(float4*)&atts[0] = *(const float4*)(att_src + tx * 8);
    *(float4*)&atts[4] = *(const float4*)(att_src + tx * 8 + 4);
    *(float4*)&attd[0] = *(const float4*)(att_dst + tx * 8);
    *(float4*)&attd[4] = *(const float4*)(att_dst + tx * 8 + 4);

    const int head = tx >> 2;

#pragma unroll
    for (int i = 0; i < 8; i++) {
        int row = rbase + ty * 8 + i;
        float h[8];
#pragma unroll
        for (int j = 0; j < 4; j++) unpack2(acc2[i][j], h[2 * j], h[2 * j + 1]);

        // per-head dot-product partials over this thread's 8 cols
        float ps = 0.f, pd = 0.f;
#pragma unroll
        for (int j = 0; j < 8; j++) { ps += h[j] * atts[j]; pd += h[j] * attd[j]; }
        // reduce across the 4 threads (tx bits 0..1) sharing this head
        ps += __shfl_xor_sync(0xffffffffu, ps, 1);
        ps += __shfl_xor_sync(0xffffffffu, ps, 2);
        pd += __shfl_xor_sync(0xffffffffu, pd, 1);
        pd += __shfl_xor_sync(0xffffffffu, pd, 2);

        float ev = ps + pd;
        ev = ev > 0.f ? ev : 0.2f * ev;
        float w = __expf(ev);   // identical in all 4 lanes of the head group

        if (row < N) {
            *(float4*)(g_h + (size_t)row * 128 + tx * 8) =
                make_float4(h[0], h[1], h[2], h[3]);
            *(float4*)(g_h + (size_t)row * 128 + tx * 8 + 4) =
                make_float4(h[4], h[5], h[6], h[7]);
            *(float4*)(out + (size_t)row * 128 + tx * 8) =
                make_float4(w * h[0], w * h[1], w * h[2], w * h[3]);
            *(float4*)(out + (size_t)row * 128 + tx * 8 + 4) =
                make_float4(w * h[4], w * h[5], w * h[6], w * h[7]);
            if ((tx & 3) == 0) {
                g_asrc[row * 4 + head] = ps;
                g_adst[row * 4 + head] = pd;
                g_s[row * 4 + head] = w;
            }
        }
    }
}

// ---------------------------------------------------------------------------
// Kernel 2: edge scatter. 1 warp/edge, lane = 4 consecutive channels
// (head = lane>>3). Unnormalized w*h[src] into out[dst] via float4 atomics.
// ---------------------------------------------------------------------------
__global__ void edge_accum(const int* __restrict__ ei,
                           float* __restrict__ out, int E, int N) {
    int e = (int)((blockIdx.x * (unsigned)blockDim.x + threadIdx.x) >> 5);
    if (e >= E) return;
    int lane = threadIdx.x & 31;

    int src = __ldg(ei + e);
    int dst = __ldg(ei + (size_t)E + e);
    if ((unsigned)src >= (unsigned)N || (unsigned)dst >= (unsigned)N) return;

    int head = lane >> 3;
    float as = __ldg(g_asrc + src * 4 + head);
    float ad = __ldg(g_adst + dst * 4 + head);
    float ev = as + ad;
    ev = ev > 0.f ? ev : 0.2f * ev;
    float w = __expf(ev);

    float4 hv = __ldg((const float4*)(g_h + (size_t)src * 128 + lane * 4));
    atomicAdd((float4*)(out + (size_t)dst * 128 + lane * 4),
              make_float4(w * hv.x, w * hv.y, w * hv.z, w * hv.w));
    if ((lane & 7) == 0) atomicAdd(g_s + dst * 4 + head, w);
}

// ---------------------------------------------------------------------------
// Kernel 3: out = tanh(out / (s + 1e-16) + bias).
// ---------------------------------------------------------------------------
__global__ void finalize(float* __restrict__ out,
                         const float* __restrict__ bias, int N) {
    int i = blockIdx.x * blockDim.x + threadIdx.x;   // float4 index
    int total = N * 32;
    if (i >= total) return;
    int node = i >> 5;
    int q = i & 31;
    float s = g_s[node * 4 + (q >> 3)] + 1e-16f;
    float inv = 1.0f / s;
    float4 v = *(float4*)(out + (size_t)i * 4);
    float4 b = *(const float4*)(bias + q * 4);
    v.x = tanhf(v.x * inv + b.x);
    v.y = tanhf(v.y * inv + b.y);
    v.z = tanhf(v.z * inv + b.z);
    v.w = tanhf(v.w * inv + b.w);
    *(float4*)(out + (size_t)i * 4) = v;
}

// ---------------------------------------------------------------------------
extern "C" void kernel_launch(void* const* d_in, const int* in_sizes, int n_in,
                              void* d_out, int out_size) {
    const float* x = (const float*)d_in[0];
    const int* ei = (const int*)d_in[1];
    const float* W = (const float*)d_in[2];
    const float* att_src = (const float*)d_in[3];
    const float* att_dst = (const float*)d_in[4];
    const float* bias = (const float*)d_in[5];
    float* out = (float*)d_out;

    int N = in_sizes[0] / 128;
    int E = in_sizes[1] / 2;

    gemm_fused<<<(N + 127) / 128, 256>>>(x, W, att_src, att_dst, out, N);
    {
        long long threads = (long long)E * 32;
        edge_accum<<<(int)((threads + 255) / 256), 256>>>(ei, out, E, N);
    }
    {
        long long threads = (long long)N * 32;
        finalize<<<(int)((threads + 255) / 256), 256>>>(out, bias, N);
    }
}

// round 4
// speedup vs baseline: 1.4804x; 1.4804x over previous
#include <cuda_runtime.h>

// ---------------------------------------------------------------------------
// GAT forward, CSR-gather pipeline (7 launches):
//   1) gemm_fused  : h = x@W via packed f32x2 FMA; epilogue computes per-node
//                    a_src/a_dst and stores h.
//   2) zero_cnt    : degree counts = 0
//   3) count_deg   : atomic degree histogram over dst
//   4) scan_p1/p2/p3 : exclusive prefix sum -> offsets + cursors
//   5) scatter_csr : csr[pos] = src  (atomic cursor per dst)
//   6) gather      : per-dst warp accumulates sum(w*h[src]) + self loop,
//                    normalizes, applies bias+tanh, writes out. NO float atomics.
// Softmax max-shift skipped: |e| bounded (~10), exp cannot overflow fp32;
// result identical after normalization.
// ---------------------------------------------------------------------------

#define NMAX 100000
#define EMAX 1600000

__device__ __align__(16) float g_h[(size_t)NMAX * 128];
__device__ __align__(16) float g_asrc[NMAX * 4];
__device__ __align__(16) float g_adst[NMAX * 4];
__device__ int g_cnt[NMAX];
__device__ int g_off[NMAX + 1];
__device__ int g_cur[NMAX];
__device__ int g_bsum[256];
__device__ int g_csr[EMAX];

__device__ __forceinline__ unsigned long long pack2(float lo, float hi) {
    unsigned long long r;
    asm("mov.b64 %0, {%1, %2};" : "=l"(r) : "f"(lo), "f"(hi));
    return r;
}
__device__ __forceinline__ void unpack2(unsigned long long v, float& lo, float& hi) {
    asm("mov.b64 {%0, %1}, %2;" : "=f"(lo), "=f"(hi) : "l"(v));
}
__device__ __forceinline__ void ffma2(unsigned long long& d,
                                      unsigned long long a,
                                      unsigned long long b) {
    asm("fma.rn.f32x2 %0, %1, %2, %0;" : "+l"(d) : "l"(a), "l"(b));
}
__device__ __forceinline__ float leaky(float v) { return v > 0.f ? v : 0.2f * v; }

// ---------------------------------------------------------------------------
// Kernel 1: GEMM + attention-logit epilogue. 512 threads, 128x128 tile,
// 4 rows x 8 cols per thread, packed f32x2 accumulators (16 regs of pairs).
// ---------------------------------------------------------------------------
__global__ __launch_bounds__(512, 1)
void gemm_fused(const float* __restrict__ x, const float* __restrict__ W,
                const float* __restrict__ att_src,
                const float* __restrict__ att_dst, int N) {
    __shared__ float sx[128][33];
    __shared__ float sW[32][128];

    const int tid = threadIdx.x;
    const int rbase = blockIdx.x * 128;
    const int tx = tid & 15;    // col group: cols tx*8..tx*8+7 (one head)
    const int tyg = tid >> 4;   // row group: rows tyg*4..tyg*4+3

    unsigned long long acc2[4][4];
#pragma unroll
    for (int i = 0; i < 4; i++)
#pragma unroll
        for (int j = 0; j < 4; j++) acc2[i][j] = 0ULL;

    for (int kc = 0; kc < 128; kc += 32) {
        __syncthreads();
        for (int i = tid; i < 1024; i += 512) {       // x: 128 rows x 32 cols
            int row = i >> 3, c4 = i & 7;
            float4 v = make_float4(0.f, 0.f, 0.f, 0.f);
            if (rbase + row < N)
                v = *(const float4*)(x + (size_t)(rbase + row) * 128 + kc + c4 * 4);
            float* p = &sx[row][c4 * 4];
            p[0] = v.x; p[1] = v.y; p[2] = v.z; p[3] = v.w;
        }
        for (int i = tid; i < 1024; i += 512) {       // W: 32 rows x 128 cols
            int row = i >> 5, c4 = i & 31;
            *(float4*)&sW[row][c4 * 4] =
                *(const float4*)(W + (size_t)(kc + row) * 128 + c4 * 4);
        }
        __syncthreads();

#pragma unroll
        for (int k = 0; k < 32; k++) {
            ulonglong2 b01 = *(const ulonglong2*)&sW[k][tx * 8];
            ulonglong2 b23 = *(const ulonglong2*)&sW[k][tx * 8 + 4];
            unsigned long long b2[4] = {b01.x, b01.y, b23.x, b23.y};
#pragma unroll
            for (int i = 0; i < 4; i++) {
                float av = sx[tyg * 4 + i][k];
                unsigned long long a2 = pack2(av, av);
#pragma unroll
                for (int j = 0; j < 4; j++) ffma2(acc2[i][j], a2, b2[j]);
            }
        }
    }

    // epilogue: h + per-head logit partials
    float atts[8], attd[8];
    *(float4*)&atts[0] = *(const float4*)(att_src + tx * 8);
    *(float4*)&atts[4] = *(const float4*)(att_src + tx * 8 + 4);
    *(float4*)&attd[0] = *(const float4*)(att_dst + tx * 8);
    *(float4*)&attd[4] = *(const float4*)(att_dst + tx * 8 + 4);
    const int head = tx >> 2;

#pragma unroll
    for (int i = 0; i < 4; i++) {
        int row = rbase + tyg * 4 + i;
        float h[8];
#pragma unroll
        for (int j = 0; j < 4; j++) unpack2(acc2[i][j], h[2 * j], h[2 * j + 1]);

        float ps = 0.f, pd = 0.f;
#pragma unroll
        for (int j = 0; j < 8; j++) { ps += h[j] * atts[j]; pd += h[j] * attd[j]; }
        ps += __shfl_xor_sync(0xffffffffu, ps, 1);
        ps += __shfl_xor_sync(0xffffffffu, ps, 2);
        pd += __shfl_xor_sync(0xffffffffu, pd, 1);
        pd += __shfl_xor_sync(0xffffffffu, pd, 2);

        if (row < N) {
            *(float4*)(g_h + (size_t)row * 128 + tx * 8) =
                make_float4(h[0], h[1], h[2], h[3]);
            *(float4*)(g_h + (size_t)row * 128 + tx * 8 + 4) =
                make_float4(h[4], h[5], h[6], h[7]);
            if ((tx & 3) == 0) {
                g_asrc[row * 4 + head] = ps;
                g_adst[row * 4 + head] = pd;
            }
        }
    }
}

// ---------------------------------------------------------------------------
// CSR build
// ---------------------------------------------------------------------------
__global__ void zero_cnt(int N) {
    int i = blockIdx.x * blockDim.x + threadIdx.x;
    if (i < N) g_cnt[i] = 0;
}

__global__ void count_deg(const int* __restrict__ ei, int E, int N) {
    int e = blockIdx.x * blockDim.x + threadIdx.x;
    if (e >= E) return;
    int dst = __ldg(ei + (size_t)E + e);
    if ((unsigned)dst < (unsigned)N) atomicAdd(&g_cnt[dst], 1);
}

// phase 1: per-1024-block inclusive scan; partial to g_off[i+1], total to g_bsum
__global__ void scan_p1(int N) {
    __shared__ int warp_sums[32];
    int b = blockIdx.x, t = threadIdx.x;
    int i = b * 1024 + t;
    int v = (i < N) ? g_cnt[i] : 0;
    int lane = t & 31, wid = t >> 5;
    int sc = v;
#pragma unroll
    for (int o = 1; o < 32; o <<= 1) {
        int u = __shfl_up_sync(0xffffffffu, sc, o);
        if (lane >= o) sc += u;
    }
    if (lane == 31) warp_sums[wid] = sc;
    __syncthreads();
    if (wid == 0) {
        int ws = warp_sums[lane];
#pragma unroll
        for (int o = 1; o < 32; o <<= 1) {
            int u = __shfl_up_sync(0xffffffffu, ws, o);
            if (lane >= o) ws += u;
        }
        warp_sums[lane] = ws;
    }
    __syncthreads();
    int incl = sc + (wid > 0 ? warp_sums[wid - 1] : 0);
    if (i < N) g_off[i + 1] = incl;
    if (t == 1023) g_bsum[b] = incl;
}

// phase 2: exclusive scan of block sums (single thread; <=128 blocks)
__global__ void scan_p2(int nb) {
    if (threadIdx.x == 0 && blockIdx.x == 0) {
        int run = 0;
        for (int b = 0; b < nb; b++) {
            int t = g_bsum[b];
            g_bsum[b] = run;
            run += t;
        }
        g_off[0] = 0;
    }
}

// phase 3: finalize offsets and init cursors (cursor[i] = off[i])
__global__ void scan_p3(int N) {
    int i = blockIdx.x * blockDim.x + threadIdx.x;
    if (i >= N) return;
    int incl = g_off[i + 1] + g_bsum[i >> 10];
    g_off[i + 1] = incl;
    g_cur[i] = incl - g_cnt[i];
}

__global__ void scatter_csr(const int* __restrict__ ei, int E, int N) {
    int e = blockIdx.x * blockDim.x + threadIdx.x;
    if (e >= E) return;
    int src = __ldg(ei + e);
    int dst = __ldg(ei + (size_t)E + e);
    if ((unsigned)src >= (unsigned)N || (unsigned)dst >= (unsigned)N) return;
    int pos = atomicAdd(&g_cur[dst], 1);
    g_csr[pos] = src;
}

// ---------------------------------------------------------------------------
// Gather: 1 warp per dst node. Accumulate sum(w * h[src]) + self loop,
// normalize, bias + tanh, one write. Zero float atomics.
// ---------------------------------------------------------------------------
__global__ void gather(const float* __restrict__ bias,
                       float* __restrict__ out, int N) {
    int node = (int)((blockIdx.x * (unsigned)blockDim.x + threadIdx.x) >> 5);
    if (node >= N) return;
    int lane = threadIdx.x & 31;
    int head = lane >> 3;

    float ad = __ldg(g_adst + node * 4 + head);
    float4 acc = make_float4(0.f, 0.f, 0.f, 0.f);
    float s = 0.f;

    int beg = g_off[node], end = g_off[node + 1];
    for (int i = beg; i < end; i += 32) {
        int m = end - i;
        if (m > 32) m = 32;
        int srcv = (lane < m) ? g_csr[i + lane] : 0;
        int j = 0;
        for (; j + 2 <= m; j += 2) {           // 2-edge software pipeline (MLP=2)
            int s0 = __shfl_sync(0xffffffffu, srcv, j);
            int s1 = __shfl_sync(0xffffffffu, srcv, j + 1);
            float as0 = __ldg(g_asrc + s0 * 4 + head);
            float as1 = __ldg(g_asrc + s1 * 4 + head);
            float4 h0 = __ldg((const float4*)(g_h + (size_t)s0 * 128 + lane * 4));
            float4 h1 = __ldg((const float4*)(g_h + (size_t)s1 * 128 + lane * 4));
            float w0 = __expf(leaky(as0 + ad));
            float w1 = __expf(leaky(as1 + ad));
            acc.x += w0 * h0.x; acc.y += w0 * h0.y;
            acc.z += w0 * h0.z; acc.w += w0 * h0.w; s += w0;
            acc.x += w1 * h1.x; acc.y += w1 * h1.y;
            acc.z += w1 * h1.z; acc.w += w1 * h1.w; s += w1;
        }
        if (j < m) {
            int s0 = __shfl_sync(0xffffffffu, srcv, j);
            float as0 = __ldg(g_asrc + s0 * 4 + head);
            float4 h0 = __ldg((const float4*)(g_h + (size_t)s0 * 128 + lane * 4));
            float w0 = __expf(leaky(as0 + ad));
            acc.x += w0 * h0.x; acc.y += w0 * h0.y;
            acc.z += w0 * h0.z; acc.w += w0 * h0.w; s += w0;
        }
    }

    // self loop
    {
        float asl = __ldg(g_asrc + node * 4 + head);
        float wl = __expf(leaky(asl + ad));
        float4 hd = *(const float4*)(g_h + (size_t)node * 128 + lane * 4);
        acc.x += wl * hd.x; acc.y += wl * hd.y;
        acc.z += wl * hd.z; acc.w += wl * hd.w; s += wl;
    }

    float inv = 1.0f / (s + 1e-16f);
    float4 b = __ldg((const float4*)(bias + lane * 4));
    float4 o;
    o.x = tanhf(acc.x * inv + b.x);
    o.y = tanhf(acc.y * inv + b.y);
    o.z = tanhf(acc.z * inv + b.z);
    o.w = tanhf(acc.w * inv + b.w);
    *(float4*)(out + (size_t)node * 128 + lane * 4) = o;
}

// ---------------------------------------------------------------------------
extern "C" void kernel_launch(void* const* d_in, const int* in_sizes, int n_in,
                              void* d_out, int out_size) {
    const float* x = (const float*)d_in[0];
    const int* ei = (const int*)d_in[1];
    const float* W = (const float*)d_in[2];
    const float* att_src = (const float*)d_in[3];
    const float* att_dst = (const float*)d_in[4];
    const float* bias = (const float*)d_in[5];
    float* out = (float*)d_out;

    int N = in_sizes[0] / 128;
    int E = in_sizes[1] / 2;
    int nb = (N + 1023) / 1024;

    gemm_fused<<<(N + 127) / 128, 512>>>(x, W, att_src, att_dst, N);
    zero_cnt<<<(N + 255) / 256, 256>>>(N);
    count_deg<<<(E + 255) / 256, 256>>>(ei, E, N);
    scan_p1<<<nb, 1024>>>(N);
    scan_p2<<<1, 32>>>(nb);
    scan_p3<<<(N + 255) / 256, 256>>>(N);
    scatter_csr<<<(E + 255) / 256, 256>>>(ei, E, N);
    {
        long long threads = (long long)N * 32;
        gather<<<(int)((threads + 255) / 256), 256>>>(bias, out, N);
    }
}

// round 6
// speedup vs baseline: 1.6973x; 1.1465x over previous
#include <cuda_runtime.h>

// ---------------------------------------------------------------------------
// GAT forward, CSR-gather pipeline with capture-forked concurrency:
//
//   stream 0 : gemm_fused (h = x@W, f32x2 FMA; epilogue emits a_src/a_dst)
//   stream s2: zero -> count -> scan(3) -> scatter_csr   (edge_index only)
//   join     : gather (per-dst warp: sum w*h[src] + self loop, normalize,
//                      bias+tanh, single write; zero float atomics)
//
// Softmax max-shift skipped: |e| bounded (~10), exp cannot overflow fp32;
// result identical after normalization.
// ---------------------------------------------------------------------------

#define NMAX 100000
#define EMAX 1600000

__device__ __align__(16) float g_h[(size_t)NMAX * 128];
__device__ __align__(16) float g_asrc[NMAX * 4];
__device__ __align__(16) float g_adst[NMAX * 4];
__device__ int g_cnt[NMAX];
__device__ int g_off[NMAX + 1];
__device__ int g_cur[NMAX];
__device__ int g_bsum[256];
__device__ int g_csr[EMAX];

__device__ __forceinline__ unsigned long long pack2(float lo, float hi) {
    unsigned long long r;
    asm("mov.b64 %0, {%1, %2};" : "=l"(r) : "f"(lo), "f"(hi));
    return r;
}
__device__ __forceinline__ void unpack2(unsigned long long v, float& lo, float& hi) {
    asm("mov.b64 {%0, %1}, %2;" : "=f"(lo), "=f"(hi) : "l"(v));
}
__device__ __forceinline__ void ffma2(unsigned long long& d,
                                      unsigned long long a,
                                      unsigned long long b) {
    asm("fma.rn.f32x2 %0, %1, %2, %0;" : "+l"(d) : "l"(a), "l"(b));
}
__device__ __forceinline__ float leaky(float v) { return v > 0.f ? v : 0.2f * v; }

// ---------------------------------------------------------------------------
// Kernel 1: GEMM + attention-logit epilogue. 512 threads, 128x128 tile,
// 4 rows x 8 cols per thread, packed f32x2 accumulators. Register-prefetch
// software pipeline across the 4 K-chunks.
// ---------------------------------------------------------------------------
__global__ __launch_bounds__(512, 1)
void gemm_fused(const float* __restrict__ x, const float* __restrict__ W,
                const float* __restrict__ att_src,
                const float* __restrict__ att_dst, int N) {
    __shared__ float sx[128][33];
    __shared__ float sW[32][128];

    const int tid = threadIdx.x;
    const int rbase = blockIdx.x * 128;
    const int tx = tid & 15;    // col group: cols tx*8..tx*8+7 (one head)
    const int tyg = tid >> 4;   // row group: rows tyg*4..tyg*4+3

    // staging geometry (fixed per thread across chunks)
    const int xi0 = tid, xi1 = tid + 512;           // x tile items (1024 total)
    const int xr0 = xi0 >> 3, xc0 = (xi0 & 7) * 4;
    const int xr1 = xi1 >> 3, xc1 = (xi1 & 7) * 4;
    const int wi0 = tid, wi1 = tid + 512;           // W chunk items
    const int wr0 = wi0 >> 5, wc0 = (wi0 & 31) * 4;
    const int wr1 = wi1 >> 5, wc1 = (wi1 & 31) * 4;
    const bool xv0 = (rbase + xr0) < N;
    const bool xv1 = (rbase + xr1) < N;

    unsigned long long acc2[4][4];
#pragma unroll
    for (int i = 0; i < 4; i++)
#pragma unroll
        for (int j = 0; j < 4; j++) acc2[i][j] = 0ULL;

    float4 rx0, rx1, rw0, rw1;
    // preload chunk 0
    {
        const int kc = 0;
        rx0 = xv0 ? *(const float4*)(x + (size_t)(rbase + xr0) * 128 + kc + xc0)
                  : make_float4(0.f, 0.f, 0.f, 0.f);
        rx1 = xv1 ? *(const float4*)(x + (size_t)(rbase + xr1) * 128 + kc + xc1)
                  : make_float4(0.f, 0.f, 0.f, 0.f);
        rw0 = *(const float4*)(W + (size_t)(kc + wr0) * 128 + wc0);
        rw1 = *(const float4*)(W + (size_t)(kc + wr1) * 128 + wc1);
    }

#pragma unroll
    for (int c = 0; c < 4; c++) {
        // store staged regs -> smem
        { float* p = &sx[xr0][xc0]; p[0]=rx0.x; p[1]=rx0.y; p[2]=rx0.z; p[3]=rx0.w; }
        { float* p = &sx[xr1][xc1]; p[0]=rx1.x; p[1]=rx1.y; p[2]=rx1.z; p[3]=rx1.w; }
        *(float4*)&sW[wr0][wc0] = rw0;
        *(float4*)&sW[wr1][wc1] = rw1;
        __syncthreads();

        // prefetch next chunk while computing this one
        if (c < 3) {
            const int kc = (c + 1) * 32;
            rx0 = xv0 ? *(const float4*)(x + (size_t)(rbase + xr0) * 128 + kc + xc0)
                      : make_float4(0.f, 0.f, 0.f, 0.f);
            rx1 = xv1 ? *(const float4*)(x + (size_t)(rbase + xr1) * 128 + kc + xc1)
                      : make_float4(0.f, 0.f, 0.f, 0.f);
            rw0 = *(const float4*)(W + (size_t)(kc + wr0) * 128 + wc0);
            rw1 = *(const float4*)(W + (size_t)(kc + wr1) * 128 + wc1);
        }

#pragma unroll
        for (int k = 0; k < 32; k++) {
            ulonglong2 b01 = *(const ulonglong2*)&sW[k][tx * 8];
            ulonglong2 b23 = *(const ulonglong2*)&sW[k][tx * 8 + 4];
            unsigned long long b2[4] = {b01.x, b01.y, b23.x, b23.y};
#pragma unroll
            for (int i = 0; i < 4; i++) {
                float av = sx[tyg * 4 + i][k];
                unsigned long long a2 = pack2(av, av);
#pragma unroll
                for (int j = 0; j < 4; j++) ffma2(acc2[i][j], a2, b2[j]);
            }
        }
        __syncthreads();
    }

    // epilogue: h + per-head logit partials
    float atts[8], attd[8];
    *(float4*)&atts[0] = *(const float4*)(att_src + tx * 8);
    *(float4*)&atts[4] = *(const float4*)(att_src + tx * 8 + 4);
    *(float4*)&attd[0] = *(const float4*)(att_dst + tx * 8);
    *(float4*)&attd[4] = *(const float4*)(att_dst + tx * 8 + 4);
    const int head = tx >> 2;

#pragma unroll
    for (int i = 0; i < 4; i++) {
        int row = rbase + tyg * 4 + i;
        float h[8];
#pragma unroll
        for (int j = 0; j < 4; j++) unpack2(acc2[i][j], h[2 * j], h[2 * j + 1]);

        float ps = 0.f, pd = 0.f;
#pragma unroll
        for (int j = 0; j < 8; j++) { ps += h[j] * atts[j]; pd += h[j] * attd[j]; }
        ps += __shfl_xor_sync(0xffffffffu, ps, 1);
        ps += __shfl_xor_sync(0xffffffffu, ps, 2);
        pd += __shfl_xor_sync(0xffffffffu, pd, 1);
        pd += __shfl_xor_sync(0xffffffffu, pd, 2);

        if (row < N) {
            *(float4*)(g_h + (size_t)row * 128 + tx * 8) =
                make_float4(h[0], h[1], h[2], h[3]);
            *(float4*)(g_h + (size_t)row * 128 + tx * 8 + 4) =
                make_float4(h[4], h[5], h[6], h[7]);
            if ((tx & 3) == 0) {
                g_asrc[row * 4 + head] = ps;
                g_adst[row * 4 + head] = pd;
            }
        }
    }
}

// ---------------------------------------------------------------------------
// CSR build (runs on forked stream, hidden under the GEMM)
// ---------------------------------------------------------------------------
__global__ void zero_cnt(int N) {
    int i = blockIdx.x * blockDim.x + threadIdx.x;
    if (i < N) g_cnt[i] = 0;
}

__global__ void count_deg(const int* __restrict__ ei, int E, int N) {
    int e = blockIdx.x * blockDim.x + threadIdx.x;
    if (e >= E) return;
    int dst = __ldg(ei + (size_t)E + e);
    if ((unsigned)dst < (unsigned)N) atomicAdd(&g_cnt[dst], 1);
}

__global__ void scan_p1(int N) {
    __shared__ int warp_sums[32];
    int b = blockIdx.x, t = threadIdx.x;
    int i = b * 1024 + t;
    int v = (i < N) ? g_cnt[i] : 0;
    int lane = t & 31, wid = t >> 5;
    int sc = v;
#pragma unroll
    for (int o = 1; o < 32; o <<= 1) {
        int u = __shfl_up_sync(0xffffffffu, sc, o);
        if (lane >= o) sc += u;
    }
    if (lane == 31) warp_sums[wid] = sc;
    __syncthreads();
    if (wid == 0) {
        int ws = warp_sums[lane];
#pragma unroll
        for (int o = 1; o < 32; o <<= 1) {
            int u = __shfl_up_sync(0xffffffffu, ws, o);
            if (lane >= o) ws += u;
        }
        warp_sums[lane] = ws;
    }
    __syncthreads();
    int incl = sc + (wid > 0 ? warp_sums[wid - 1] : 0);
    if (i < N) g_off[i + 1] = incl;
    if (t == 1023) g_bsum[b] = incl;
}

__global__ void scan_p2(int nb) {
    if (threadIdx.x == 0 && blockIdx.x == 0) {
        int run = 0;
        for (int b = 0; b < nb; b++) {
            int t = g_bsum[b];
            g_bsum[b] = run;
            run += t;
        }
        g_off[0] = 0;
    }
}

__global__ void scan_p3(int N) {
    int i = blockIdx.x * blockDim.x + threadIdx.x;
    if (i >= N) return;
    int incl = g_off[i + 1] + g_bsum[i >> 10];
    g_off[i + 1] = incl;
    g_cur[i] = incl - g_cnt[i];
}

__global__ void scatter_csr(const int* __restrict__ ei, int E, int N) {
    int e = blockIdx.x * blockDim.x + threadIdx.x;
    if (e >= E) return;
    int src = __ldg(ei + e);
    int dst = __ldg(ei + (size_t)E + e);
    if ((unsigned)src >= (unsigned)N || (unsigned)dst >= (unsigned)N) return;
    int pos = atomicAdd(&g_cur[dst], 1);
    g_csr[pos] = src;
}

// ---------------------------------------------------------------------------
// Gather: 1 warp per dst node, 4-deep load pipeline.
// ---------------------------------------------------------------------------
__global__ void gather(const float* __restrict__ bias,
                       float* __restrict__ out, int N) {
    int node = (int)((blockIdx.x * (unsigned)blockDim.x + threadIdx.x) >> 5);
    if (node >= N) return;
    int lane = threadIdx.x & 31;
    int head = lane >> 3;

    float ad = __ldg(g_adst + node * 4 + head);
    float4 acc = make_float4(0.f, 0.f, 0.f, 0.f);
    float s = 0.f;

    int beg = g_off[node], end = g_off[node + 1];
    for (int i = beg; i < end; i += 32) {
        int m = end - i;
        if (m > 32) m = 32;
        int srcv = (lane < m) ? g_csr[i + lane] : 0;
        int j = 0;
        for (; j + 4 <= m; j += 4) {   // 4 independent load pairs (MLP=4)
            int s0 = __shfl_sync(0xffffffffu, srcv, j);
            int s1 = __shfl_sync(0xffffffffu, srcv, j + 1);
            int s2 = __shfl_sync(0xffffffffu, srcv, j + 2);
            int s3 = __shfl_sync(0xffffffffu, srcv, j + 3);
            float as0 = __ldg(g_asrc + s0 * 4 + head);
            float as1 = __ldg(g_asrc + s1 * 4 + head);
            float as2 = __ldg(g_asrc + s2 * 4 + head);
            float as3 = __ldg(g_asrc + s3 * 4 + head);
            float4 h0 = __ldg((const float4*)(g_h + (size_t)s0 * 128 + lane * 4));
            float4 h1 = __ldg((const float4*)(g_h + (size_t)s1 * 128 + lane * 4));
            float4 h2 = __ldg((const float4*)(g_h + (size_t)s2 * 128 + lane * 4));
            float4 h3 = __ldg((const float4*)(g_h + (size_t)s3 * 128 + lane * 4));
            float w0 = __expf(leaky(as0 + ad));
            float w1 = __expf(leaky(as1 + ad));
            float w2 = __expf(leaky(as2 + ad));
            float w3 = __expf(leaky(as3 + ad));
            acc.x += w0*h0.x; acc.y += w0*h0.y; acc.z += w0*h0.z; acc.w += w0*h0.w;
            acc.x += w1*h1.x; acc.y += w1*h1.y; acc.z += w1*h1.z; acc.w += w1*h1.w;
            acc.x += w2*h2.x; acc.y += w2*h2.y; acc.z += w2*h2.z; acc.w += w2*h2.w;
            acc.x += w3*h3.x; acc.y += w3*h3.y; acc.z += w3*h3.z; acc.w += w3*h3.w;
            s += w0 + w1 + w2 + w3;
        }
        for (; j < m; j++) {
            int s0 = __shfl_sync(0xffffffffu, srcv, j);
            float as0 = __ldg(g_asrc + s0 * 4 + head);
            float4 h0 = __ldg((const float4*)(g_h + (size_t)s0 * 128 + lane * 4));
            float w0 = __expf(leaky(as0 + ad));
            acc.x += w0*h0.x; acc.y += w0*h0.y; acc.z += w0*h0.z; acc.w += w0*h0.w;
            s += w0;
        }
    }

    // self loop
    {
        float asl = __ldg(g_asrc + node * 4 + head);
        float wl = __expf(leaky(asl + ad));
        float4 hd = *(const float4*)(g_h + (size_t)node * 128 + lane * 4);
        acc.x += wl*hd.x; acc.y += wl*hd.y; acc.z += wl*hd.z; acc.w += wl*hd.w;
        s += wl;
    }

    float inv = 1.0f / (s + 1e-16f);
    float4 b = __ldg((const float4*)(bias + lane * 4));
    float4 o;
    o.x = tanhf(acc.x * inv + b.x);
    o.y = tanhf(acc.y * inv + b.y);
    o.z = tanhf(acc.z * inv + b.z);
    o.w = tanhf(acc.w * inv + b.w);
    *(float4*)(out + (size_t)node * 128 + lane * 4) = o;
}

// ---------------------------------------------------------------------------
extern "C" void kernel_launch(void* const* d_in, const int* in_sizes, int n_in,
                              void* d_out, int out_size) {
    const float* x = (const float*)d_in[0];
    const int* ei = (const int*)d_in[1];
    const float* W = (const float*)d_in[2];
    const float* att_src = (const float*)d_in[3];
    const float* att_dst = (const float*)d_in[4];
    const float* bias = (const float*)d_in[5];
    float* out = (float*)d_out;

    int N = in_sizes[0] / 128;
    int E = in_sizes[1] / 2;
    int nb = (N + 1023) / 1024;

    // fork a side stream off the capture-origin stream (event fork/join idiom;
    // stream/events are host objects, no device memory, not destroyed so that
    // capture state is never invalidated)
    cudaStream_t s2;
    cudaEvent_t evF, evJ;
    cudaStreamCreateWithFlags(&s2, cudaStreamNonBlocking);
    cudaEventCreateWithFlags(&evF, cudaEventDisableTiming);
    cudaEventCreateWithFlags(&evJ, cudaEventDisableTiming);

    cudaEventRecord(evF, 0);
    cudaStreamWaitEvent(s2, evF, 0);

    // CSR chain on s2 (independent of GEMM)
    zero_cnt<<<(N + 255) / 256, 256, 0, s2>>>(N);
    count_deg<<<(E + 255) / 256, 256, 0, s2>>>(ei, E, N);
    scan_p1<<<nb, 1024, 0, s2>>>(N);
    scan_p2<<<1, 32, 0, s2>>>(nb);
    scan_p3<<<(N + 255) / 256, 256, 0, s2>>>(N);
    scatter_csr<<<(E + 255) / 256, 256, 0, s2>>>(ei, E, N);

    // GEMM on origin stream, concurrent with the CSR chain
    gemm_fused<<<(N + 127) / 128, 512>>>(x, W, att_src, att_dst, N);

    cudaEventRecord(evJ, s2);
    cudaStreamWaitEvent(0, evJ, 0);

    {
        long long threads = (long long)N * 32;
        gather<<<(int)((threads + 255) / 256), 256>>>(bias, out, N);
    }
}

// round 9
// speedup vs baseline: 1.7773x; 1.0471x over previous
#include <cuda_runtime.h>

// ---------------------------------------------------------------------------
// GAT forward, CSR-gather pipeline with capture-forked concurrency:
//
//   stream 0 : gemm_fused (h = x@W, f32x2 FMA; epilogue emits a_src/a_dst)
//   stream s2: zero -> count -> scan(3) -> scatter_csr   (edge_index only)
//   join     : gather (per-dst warp: sum w*h[src] + self loop, normalize,
//                      bias+tanh, single write; zero float atomics)
//
// Softmax max-shift skipped: |e| bounded (~10), exp cannot overflow fp32;
// result identical after normalization.
// ---------------------------------------------------------------------------

#define NMAX 100000
#define EMAX 1600000

__device__ __align__(16) float g_h[(size_t)NMAX * 128];
__device__ __align__(16) float g_asrc[NMAX * 4];
__device__ __align__(16) float g_adst[NMAX * 4];
__device__ int g_cnt[NMAX];
__device__ int g_off[NMAX + 1];
__device__ int g_cur[NMAX];
__device__ int g_bsum[256];
__device__ int g_csr[EMAX];

__device__ __forceinline__ unsigned long long pack2(float lo, float hi) {
    unsigned long long r;
    asm("mov.b64 %0, {%1, %2};" : "=l"(r) : "f"(lo), "f"(hi));
    return r;
}
__device__ __forceinline__ void unpack2(unsigned long long v, float& lo, float& hi) {
    asm("mov.b64 {%0, %1}, %2;" : "=f"(lo), "=f"(hi) : "l"(v));
}
__device__ __forceinline__ void ffma2(unsigned long long& d,
                                      unsigned long long a,
                                      unsigned long long b) {
    asm("fma.rn.f32x2 %0, %1, %2, %0;" : "+l"(d) : "l"(a), "l"(b));
}
__device__ __forceinline__ float leaky(float v) { return v > 0.f ? v : 0.2f * v; }

// ---------------------------------------------------------------------------
// Kernel 1: GEMM + attention-logit epilogue.
// 64-row x 128-col tile, 256 threads, 4 rows x 8 cols per thread, packed
// f32x2 accumulators, register-prefetch pipeline across the 4 K-chunks.
// ~80 regs/thread -> 3 CTAs/SM: staging latency of one CTA hides under the
// compute of co-resident CTAs, and the wave tail shrinks.
// ---------------------------------------------------------------------------
__global__ __launch_bounds__(256)
void gemm_fused(const float* __restrict__ x, const float* __restrict__ W,
                const float* __restrict__ att_src,
                const float* __restrict__ att_dst, int N) {
    __shared__ float sx[64][33];    // [row][k-within-chunk], +1 pad
    __shared__ float sW[32][128];   // [k-within-chunk][col]

    const int tid = threadIdx.x;
    const int rbase = blockIdx.x * 64;
    const int tx = tid & 15;    // col group: cols tx*8..tx*8+7 (one head)
    const int tyg = tid >> 4;   // row group: rows tyg*4..tyg*4+3

    // staging geometry (fixed per thread across chunks)
    // x tile: 64 rows x 32 cols = 512 float4 items; 2 per thread
    const int xi0 = tid, xi1 = tid + 256;
    const int xr0 = xi0 >> 3, xc0 = (xi0 & 7) * 4;
    const int xr1 = xi1 >> 3, xc1 = (xi1 & 7) * 4;
    const bool xv0 = (rbase + xr0) < N;
    const bool xv1 = (rbase + xr1) < N;
    // W chunk: 32 rows x 128 cols = 1024 float4 items; 4 per thread
    const int wr0 = (tid) >> 5,         wc0 = (tid & 31) * 4;
    const int wr1 = (tid + 256) >> 5,   wc1 = wc0;
    const int wr2 = (tid + 512) >> 5,   wc2 = wc0;
    const int wr3 = (tid + 768) >> 5,   wc3 = wc0;

    unsigned long long acc2[4][4];
#pragma unroll
    for (int i = 0; i < 4; i++)
#pragma unroll
        for (int j = 0; j < 4; j++) acc2[i][j] = 0ULL;

    float4 rx0, rx1, rw0, rw1, rw2, rw3;
    // preload chunk 0
    {
        rx0 = xv0 ? *(const float4*)(x + (size_t)(rbase + xr0) * 128 + xc0)
                  : make_float4(0.f, 0.f, 0.f, 0.f);
        rx1 = xv1 ? *(const float4*)(x + (size_t)(rbase + xr1) * 128 + xc1)
                  : make_float4(0.f, 0.f, 0.f, 0.f);
        rw0 = *(const float4*)(W + (size_t)wr0 * 128 + wc0);
        rw1 = *(const float4*)(W + (size_t)wr1 * 128 + wc1);
        rw2 = *(const float4*)(W + (size_t)wr2 * 128 + wc2);
        rw3 = *(const float4*)(W + (size_t)wr3 * 128 + wc3);
    }

#pragma unroll
    for (int c = 0; c < 4; c++) {
        // store staged regs -> smem
        { float* p = &sx[xr0][xc0]; p[0]=rx0.x; p[1]=rx0.y; p[2]=rx0.z; p[3]=rx0.w; }
        { float* p = &sx[xr1][xc1]; p[0]=rx1.x; p[1]=rx1.y; p[2]=rx1.z; p[3]=rx1.w; }
        *(float4*)&sW[wr0][wc0] = rw0;
        *(float4*)&sW[wr1][wc1] = rw1;
        *(float4*)&sW[wr2][wc2] = rw2;
        *(float4*)&sW[wr3][wc3] = rw3;
        __syncthreads();

        // prefetch next chunk while computing this one
        if (c < 3) {
            const int kc = (c + 1) * 32;
            rx0 = xv0 ? *(const float4*)(x + (size_t)(rbase + xr0) * 128 + kc + xc0)
                      : make_float4(0.f, 0.f, 0.f, 0.f);
            rx1 = xv1 ? *(const float4*)(x + (size_t)(rbase + xr1) * 128 + kc + xc1)
                      : make_float4(0.f, 0.f, 0.f, 0.f);
            rw0 = *(const float4*)(W + (size_t)(kc + wr0) * 128 + wc0);
            rw1 = *(const float4*)(W + (size_t)(kc + wr1) * 128 + wc1);
            rw2 = *(const float4*)(W + (size_t)(kc + wr2) * 128 + wc2);
            rw3 = *(const float4*)(W + (size_t)(kc + wr3) * 128 + wc3);
        }

#pragma unroll
        for (int k = 0; k < 32; k++) {
            ulonglong2 b01 = *(const ulonglong2*)&sW[k][tx * 8];
            ulonglong2 b23 = *(const ulonglong2*)&sW[k][tx * 8 + 4];
            unsigned long long b2[4] = {b01.x, b01.y, b23.x, b23.y};
#pragma unroll
            for (int i = 0; i < 4; i++) {
                float av = sx[tyg * 4 + i][k];
                unsigned long long a2 = pack2(av, av);
#pragma unroll
                for (int j = 0; j < 4; j++) ffma2(acc2[i][j], a2, b2[j]);
            }
        }
        __syncthreads();
    }

    // epilogue: h + per-head logit partials
    float atts[8], attd[8];
    *(float4*)&atts[0] = *(const float4*)(att_src + tx * 8);
    *(float4*)&atts[4] = *(const float4*)(att_src + tx * 8 + 4);
    *(float4*)&attd[0] = *(const float4*)(att_dst + tx * 8);
    *(float4*)&attd[4] = *(const float4*)(att_dst + tx * 8 + 4);
    const int head = tx >> 2;

#pragma unroll
    for (int i = 0; i < 4; i++) {
        int row = rbase + tyg * 4 + i;
        float h[8];
#pragma unroll
        for (int j = 0; j < 4; j++) unpack2(acc2[i][j], h[2 * j], h[2 * j + 1]);

        float ps = 0.f, pd = 0.f;
#pragma unroll
        for (int j = 0; j < 8; j++) { ps += h[j] * atts[j]; pd += h[j] * attd[j]; }
        ps += __shfl_xor_sync(0xffffffffu, ps, 1);
        ps += __shfl_xor_sync(0xffffffffu, ps, 2);
        pd += __shfl_xor_sync(0xffffffffu, pd, 1);
        pd += __shfl_xor_sync(0xffffffffu, pd, 2);

        if (row < N) {
            *(float4*)(g_h + (size_t)row * 128 + tx * 8) =
                make_float4(h[0], h[1], h[2], h[3]);
            *(float4*)(g_h + (size_t)row * 128 + tx * 8 + 4) =
                make_float4(h[4], h[5], h[6], h[7]);
            if ((tx & 3) == 0) {
                g_asrc[row * 4 + head] = ps;
                g_adst[row * 4 + head] = pd;
            }
        }
    }
}

// ---------------------------------------------------------------------------
// CSR build (runs on forked stream, hidden under the GEMM)
// ---------------------------------------------------------------------------
__global__ void zero_cnt(int N) {
    int i = blockIdx.x * blockDim.x + threadIdx.x;
    if (i < N) g_cnt[i] = 0;
}

__global__ void count_deg(const int* __restrict__ ei, int E, int N) {
    int e = blockIdx.x * blockDim.x + threadIdx.x;
    if (e >= E) return;
    int dst = __ldg(ei + (size_t)E + e);
    if ((unsigned)dst < (unsigned)N) atomicAdd(&g_cnt[dst], 1);
}

__global__ void scan_p1(int N) {
    __shared__ int warp_sums[32];
    int b = blockIdx.x, t = threadIdx.x;
    int i = b * 1024 + t;
    int v = (i < N) ? g_cnt[i] : 0;
    int lane = t & 31, wid = t >> 5;
    int sc = v;
#pragma unroll
    for (int o = 1; o < 32; o <<= 1) {
        int u = __shfl_up_sync(0xffffffffu, sc, o);
        if (lane >= o) sc += u;
    }
    if (lane == 31) warp_sums[wid] = sc;
    __syncthreads();
    if (wid == 0) {
        int ws = warp_sums[lane];
#pragma unroll
        for (int o = 1; o < 32; o <<= 1) {
            int u = __shfl_up_sync(0xffffffffu, ws, o);
            if (lane >= o) ws += u;
        }
        warp_sums[lane] = ws;
    }
    __syncthreads();
    int incl = sc + (wid > 0 ? warp_sums[wid - 1] : 0);
    if (i < N) g_off[i + 1] = incl;
    if (t == 1023) g_bsum[b] = incl;
}

__global__ void scan_p2(int nb) {
    if (threadIdx.x == 0 && blockIdx.x == 0) {
        int run = 0;
        for (int b = 0; b < nb; b++) {
            int t = g_bsum[b];
            g_bsum[b] = run;
            run += t;
        }
        g_off[0] = 0;
    }
}

__global__ void scan_p3(int N) {
    int i = blockIdx.x * blockDim.x + threadIdx.x;
    if (i >= N) return;
    int incl = g_off[i + 1] + g_bsum[i >> 10];
    g_off[i + 1] = incl;
    g_cur[i] = incl - g_cnt[i];
}

__global__ void scatter_csr(const int* __restrict__ ei, int E, int N) {
    int e = blockIdx.x * blockDim.x + threadIdx.x;
    if (e >= E) return;
    int src = __ldg(ei + e);
    int dst = __ldg(ei + (size_t)E + e);
    if ((unsigned)src >= (unsigned)N || (unsigned)dst >= (unsigned)N) return;
    int pos = atomicAdd(&g_cur[dst], 1);
    g_csr[pos] = src;
}

// ---------------------------------------------------------------------------
// Gather: 1 warp per dst node, 4-deep load pipeline.
// ---------------------------------------------------------------------------
__global__ void gather(const float* __restrict__ bias,
                       float* __restrict__ out, int N) {
    int node = (int)((blockIdx.x * (unsigned)blockDim.x + threadIdx.x) >> 5);
    if (node >= N) return;
    int lane = threadIdx.x & 31;
    int head = lane >> 3;

    float ad = __ldg(g_adst + node * 4 + head);
    float4 acc = make_float4(0.f, 0.f, 0.f, 0.f);
    float s = 0.f;

    int beg = g_off[node], end = g_off[node + 1];
    for (int i = beg; i < end; i += 32) {
        int m = end - i;
        if (m > 32) m = 32;
        int srcv = (lane < m) ? g_csr[i + lane] : 0;
        int j = 0;
        for (; j + 4 <= m; j += 4) {   // 4 independent load pairs (MLP=4)
            int s0 = __shfl_sync(0xffffffffu, srcv, j);
            int s1 = __shfl_sync(0xffffffffu, srcv, j + 1);
            int s2 = __shfl_sync(0xffffffffu, srcv, j + 2);
            int s3 = __shfl_sync(0xffffffffu, srcv, j + 3);
            float as0 = __ldg(g_asrc + s0 * 4 + head);
            float as1 = __ldg(g_asrc + s1 * 4 + head);
            float as2 = __ldg(g_asrc + s2 * 4 + head);
            float as3 = __ldg(g_asrc + s3 * 4 + head);
            float4 h0 = __ldg((const float4*)(g_h + (size_t)s0 * 128 + lane * 4));
            float4 h1 = __ldg((const float4*)(g_h + (size_t)s1 * 128 + lane * 4));
            float4 h2 = __ldg((const float4*)(g_h + (size_t)s2 * 128 + lane * 4));
            float4 h3 = __ldg((const float4*)(g_h + (size_t)s3 * 128 + lane * 4));
            float w0 = __expf(leaky(as0 + ad));
            float w1 = __expf(leaky(as1 + ad));
            float w2 = __expf(leaky(as2 + ad));
            float w3 = __expf(leaky(as3 + ad));
            acc.x += w0*h0.x; acc.y += w0*h0.y; acc.z += w0*h0.z; acc.w += w0*h0.w;
            acc.x += w1*h1.x; acc.y += w1*h1.y; acc.z += w1*h1.z; acc.w += w1*h1.w;
            acc.x += w2*h2.x; acc.y += w2*h2.y; acc.z += w2*h2.z; acc.w += w2*h2.w;
            acc.x += w3*h3.x; acc.y += w3*h3.y; acc.z += w3*h3.z; acc.w += w3*h3.w;
            s += w0 + w1 + w2 + w3;
        }
        for (; j < m; j++) {
            int s0 = __shfl_sync(0xffffffffu, srcv, j);
            float as0 = __ldg(g_asrc + s0 * 4 + head);
            float4 h0 = __ldg((const float4*)(g_h + (size_t)s0 * 128 + lane * 4));
            float w0 = __expf(leaky(as0 + ad));
            acc.x += w0*h0.x; acc.y += w0*h0.y; acc.z += w0*h0.z; acc.w += w0*h0.w;
            s += w0;
        }
    }

    // self loop
    {
        float asl = __ldg(g_asrc + node * 4 + head);
        float wl = __expf(leaky(asl + ad));
        float4 hd = *(const float4*)(g_h + (size_t)node * 128 + lane * 4);
        acc.x += wl*hd.x; acc.y += wl*hd.y; acc.z += wl*hd.z; acc.w += wl*hd.w;
        s += wl;
    }

    float inv = 1.0f / (s + 1e-16f);
    float4 b = __ldg((const float4*)(bias + lane * 4));
    float4 o;
    o.x = tanhf(acc.x * inv + b.x);
    o.y = tanhf(acc.y * inv + b.y);
    o.z = tanhf(acc.z * inv + b.z);
    o.w = tanhf(acc.w * inv + b.w);
    *(float4*)(out + (size_t)node * 128 + lane * 4) = o;
}

// ---------------------------------------------------------------------------
extern "C" void kernel_launch(void* const* d_in, const int* in_sizes, int n_in,
                              void* d_out, int out_size) {
    const float* x = (const float*)d_in[0];
    const int* ei = (const int*)d_in[1];
    const float* W = (const float*)d_in[2];
    const float* att_src = (const float*)d_in[3];
    const float* att_dst = (const float*)d_in[4];
    const float* bias = (const float*)d_in[5];
    float* out = (float*)d_out;

    int N = in_sizes[0] / 128;
    int E = in_sizes[1] / 2;
    int nb = (N + 1023) / 1024;

    // fork a side stream off the capture-origin stream (event fork/join idiom;
    // stream/events are host objects, no device memory)
    cudaStream_t s2;
    cudaEvent_t evF, evJ;
    cudaStreamCreateWithFlags(&s2, cudaStreamNonBlocking);
    cudaEventCreateWithFlags(&evF, cudaEventDisableTiming);
    cudaEventCreateWithFlags(&evJ, cudaEventDisableTiming);

    cudaEventRecord(evF, 0);
    cudaStreamWaitEvent(s2, evF, 0);

    // CSR chain on s2 (independent of GEMM)
    zero_cnt<<<(N + 255) / 256, 256, 0, s2>>>(N);
    count_deg<<<(E + 255) / 256, 256, 0, s2>>>(ei, E, N);
    scan_p1<<<nb, 1024, 0, s2>>>(N);
    scan_p2<<<1, 32, 0, s2>>>(nb);
    scan_p3<<<(N + 255) / 256, 256, 0, s2>>>(N);
    scatter_csr<<<(E + 255) / 256, 256, 0, s2>>>(ei, E, N);

    // GEMM on origin stream, concurrent with the CSR chain
    gemm_fused<<<(N + 63) / 64, 256>>>(x, W, att_src, att_dst, N);

    cudaEventRecord(evJ, s2);
    cudaStreamWaitEvent(0, evJ, 0);

    {
        long long threads = (long long)N * 32;
        gather<<<(int)((threads + 255) / 256), 256>>>(bias, out, N);
    }
}